// round 15
// baseline (speedup 1.0000x reference)
#include <cuda_runtime.h>
#include <cuda_bf16.h>

// Cosine similarity per row: out[i] = dot(q_i, d_i) / (||q_i|| * ||d_i||)
// N = 262144 rows, D = 256 fp32.
// ITERS=1 limit of the session's best design: 1024-thread blocks, 32 warps,
// each warp computes exactly ONE row (4 front-batched LDG.128 + streaming
// hints) over the block's contiguous 32-row chunk. Straight-line body, one
// barrier, then one coalesced 128B store per block. Block lifetime = max of
// 32 single-row latencies (vs max of 16 two-row chains at ITERS=2), which
// shrinks the terminal-barrier wait that round 12 showed dominates.

#define D_DIM 256
#define D4 (D_DIM / 4)
#define THREADS_PER_BLOCK 1024
#define WARPS_PER_BLOCK (THREADS_PER_BLOCK / 32)   // 32
#define ROWS_PER_BLOCK WARPS_PER_BLOCK             // 32

__global__ __launch_bounds__(THREADS_PER_BLOCK, 2)
void cosine_sim_kernel(const float4* __restrict__ q4,
                       const float4* __restrict__ d4,
                       float* __restrict__ out,
                       int n_rows) {
    __shared__ float results[ROWS_PER_BLOCK];

    const int lane = threadIdx.x & 31;
    const int warp = threadIdx.x >> 5;
    const int block_row0 = blockIdx.x * ROWS_PER_BLOCK;
    const int row = block_row0 + warp;

    if (row < n_rows) {
        const float4* qr = q4 + (size_t)row * D4;
        const float4* dr = d4 + (size_t)row * D4;

        // Front-batch the 4 LDG.128 for this row, interleaving q/d streams.
        float4 qa = __ldcs(qr + lane);
        float4 da = __ldcs(dr + lane);
        float4 qb = __ldcs(qr + lane + 32);
        float4 db = __ldcs(dr + lane + 32);

        float dot = qa.x * da.x + qa.y * da.y + qa.z * da.z + qa.w * da.w
                  + qb.x * db.x + qb.y * db.y + qb.z * db.z + qb.w * db.w;
        float qq  = qa.x * qa.x + qa.y * qa.y + qa.z * qa.z + qa.w * qa.w
                  + qb.x * qb.x + qb.y * qb.y + qb.z * qb.z + qb.w * qb.w;
        float dd  = da.x * da.x + da.y * da.y + da.z * da.z + da.w * da.w
                  + db.x * db.x + db.y * db.y + db.z * db.z + db.w * db.w;

        #pragma unroll
        for (int off = 16; off > 0; off >>= 1) {
            dot += __shfl_xor_sync(0xFFFFFFFFu, dot, off);
            qq  += __shfl_xor_sync(0xFFFFFFFFu, qq,  off);
            dd  += __shfl_xor_sync(0xFFFFFFFFu, dd,  off);
        }

        if (lane == 0) {
            results[warp] = dot * rsqrtf(qq * dd);
        }
    }

    __syncthreads();

    // One coalesced 128B store for the whole block's results.
    if (threadIdx.x < ROWS_PER_BLOCK) {
        const int orow = block_row0 + threadIdx.x;
        if (orow < n_rows) {
            __stcs(out + orow, results[threadIdx.x]);
        }
    }
}

extern "C" void kernel_launch(void* const* d_in, const int* in_sizes, int n_in,
                              void* d_out, int out_size) {
    const float4* q = (const float4*)d_in[0];
    const float4* d = (const float4*)d_in[1];
    float* out = (float*)d_out;

    const int n_rows = in_sizes[0] / D_DIM;
    const int blocks = (n_rows + ROWS_PER_BLOCK - 1) / ROWS_PER_BLOCK;

    cosine_sim_kernel<<<blocks, THREADS_PER_BLOCK>>>(q, d, out, n_rows);
}